// round 4
// baseline (speedup 1.0000x reference)
#include <cuda_runtime.h>
#include <cuda_bf16.h>

// Problem constants
#define S_DIM   384
#define N_DIM   512
#define C_DIM   32
#define CZ_DIM  128
#define M_DIM   (S_DIM * C_DIM)     // 12288  (i*32 + c)
#define K2_DIM  (C_DIM * C_DIM)     // 1024   (c*32 + d)

// Scratch: a/b projected activations, stored K-major-transposed:
// g_AT[n][i*32 + c], g_BT[n][j*32 + d]
__device__ float g_AT[N_DIM * M_DIM];
__device__ float g_BT[N_DIM * M_DIM];

// ---------------------------------------------------------------------------
// Kernel 1: LayerNorm over C=32 + projection to a (scaled by 1/512) and b.
// One warp per (s, n) row. 8 warps per block.
// ---------------------------------------------------------------------------
__global__ __launch_bounds__(256) void ln_proj_kernel(
    const float* __restrict__ m_si,
    const float* __restrict__ ln_g,
    const float* __restrict__ ln_b,
    const float* __restrict__ w_ab)
{
    __shared__ float ws[64 * 33];   // padded to kill 32-way bank conflicts

    int t = threadIdx.x;
    for (int idx = t; idx < 64 * 32; idx += 256) {
        int d = idx >> 5, c = idx & 31;
        ws[d * 33 + c] = w_ab[idx];
    }
    __syncthreads();

    int warp = t >> 5, lane = t & 31;
    int r = blockIdx.x * 8 + warp;          // row in [0, 384*512)
    int s = r >> 9;                         // N_DIM = 512
    int n = r & 511;

    float x = m_si[r * 32 + lane];

    // mean
    float sum = x;
    #pragma unroll
    for (int o = 16; o; o >>= 1) sum += __shfl_xor_sync(0xFFFFFFFFu, sum, o);
    float mu = sum * (1.0f / 32.0f);
    float dx = x - mu;

    // variance
    float v = dx * dx;
    #pragma unroll
    for (int o = 16; o; o >>= 1) v += __shfl_xor_sync(0xFFFFFFFFu, v, o);
    float rstd = rsqrtf(v * (1.0f / 32.0f) + 1e-5f);

    float mn = dx * rstd * ln_g[lane] + ln_b[lane];

    // ab[d] = sum_c mn[c] * w_ab[d][c]; lane computes d=lane (a) and d=lane+32 (b)
    float acc_a = 0.0f, acc_b = 0.0f;
    #pragma unroll
    for (int c = 0; c < 32; c++) {
        float mc = __shfl_sync(0xFFFFFFFFu, mn, c);
        acc_a += mc * ws[lane * 33 + c];
        acc_b += mc * ws[(lane + 32) * 33 + c];
    }

    // coalesced stores (lane-contiguous in m)
    g_AT[n * M_DIM + s * 32 + lane] = acc_a * (1.0f / 512.0f);  // fold 1/n_seq
    g_BT[n * M_DIM + s * 32 + lane] = acc_b;
}

// ---------------------------------------------------------------------------
// Kernel 2: fused o-tile GEMM + w_final contraction.
// Each CTA: 128x128 tile of o = AT^T * BT (K = 512), i.e. 4 i-values x 4
// j-values = 16 (i,j) pairs. Then z[pair][0..127] = W * o_vec[pair] + bias.
// 256 threads, 8x8 register blocking (strided, conflict-free scalar LDS).
// ---------------------------------------------------------------------------
#define BM 128
#define BN 128
#define KT 8
#define OSM_STRIDE (K2_DIM + 8)     // 1032 floats; 4128 B rows, 16B aligned

extern __shared__ float smem_buf[];

__global__ __launch_bounds__(256, 2) void opm_fused_kernel(
    const float* __restrict__ w_final,
    const float* __restrict__ b_final,
    float* __restrict__ z)
{
    float* As = smem_buf;                 // [KT][BM]
    float* Bs = smem_buf + KT * BM;       // [KT][BN]
    float* osm = smem_buf;                // reused: [16][OSM_STRIDE]

    int t  = threadIdx.x;
    int tm = t >> 4;                      // 0..15
    int tn = t & 15;                      // 0..15
    int m0 = blockIdx.y * BM;
    int p0 = blockIdx.x * BN;

    float acc[8][8];
    #pragma unroll
    for (int u = 0; u < 8; u++)
        #pragma unroll
        for (int v = 0; v < 8; v++) acc[u][v] = 0.0f;

    for (int k0 = 0; k0 < N_DIM; k0 += KT) {
        // cooperative tile load: 8x128 each, coalesced along m
        #pragma unroll
        for (int q = 0; q < 4; q++) {
            int idx = t + q * 256;                  // 0..1023
            int kk = idx >> 7, mm = idx & 127;
            As[kk * BM + mm] = g_AT[(k0 + kk) * M_DIM + m0 + mm];
            Bs[kk * BN + mm] = g_BT[(k0 + kk) * M_DIM + p0 + mm];
        }
        __syncthreads();

        #pragma unroll
        for (int kk = 0; kk < KT; kk++) {
            float ra[8], rb[8];
            #pragma unroll
            for (int u = 0; u < 8; u++) ra[u] = As[kk * BM + tm + u * 16];
            #pragma unroll
            for (int v = 0; v < 8; v++) rb[v] = Bs[kk * BN + tn + v * 16];
            #pragma unroll
            for (int u = 0; u < 8; u++)
                #pragma unroll
                for (int v = 0; v < 8; v++)
                    acc[u][v] += ra[u] * rb[v];
        }
        __syncthreads();
    }

    // Park o tile in SMEM, transposed into pair-major [pair][k=c*32+d] layout.
    // Thread's acc[u][v] is o at (row_local = tm + 16u, col_local = tn + 16v).
    #pragma unroll
    for (int u = 0; u < 8; u++) {
        int rl = tm + u * 16;
        #pragma unroll
        for (int v = 0; v < 8; v++) {
            int cl = tn + v * 16;
            int pair = ((rl >> 5) << 2) | (cl >> 5);
            int k    = ((rl & 31) << 5) | (cl & 31);
            osm[pair * OSM_STRIDE + k] = acc[u][v];
        }
    }
    __syncthreads();

    // Epilogue GEMM: z[pair][zz] = sum_k osm[pair][k] * w_final[zz][k] + bias
    // Each thread: 2 pairs x 4 zz outputs, K = 1024, unrolled by 4 (float4).
    int pb  = (t & 7) * 2;        // pair base: 0,2,...,14
    int zz0 = (t >> 3) * 4;       // 0,4,...,124

    float zacc[2][4];
    #pragma unroll
    for (int p = 0; p < 2; p++)
        #pragma unroll
        for (int q = 0; q < 4; q++) zacc[p][q] = 0.0f;

    const float4* Wv = reinterpret_cast<const float4*>(w_final);
    const float4* o0p = reinterpret_cast<const float4*>(&osm[pb * OSM_STRIDE]);
    const float4* o1p = reinterpret_cast<const float4*>(&osm[(pb + 1) * OSM_STRIDE]);

    #pragma unroll 4
    for (int k4 = 0; k4 < K2_DIM / 4; k4++) {
        float4 o0 = o0p[k4];
        float4 o1 = o1p[k4];
        #pragma unroll
        for (int q = 0; q < 4; q++) {
            float4 w = Wv[(zz0 + q) * (K2_DIM / 4) + k4];
            zacc[0][q] += o0.x * w.x + o0.y * w.y + o0.z * w.z + o0.w * w.w;
            zacc[1][q] += o1.x * w.x + o1.y * w.y + o1.z * w.z + o1.w * w.w;
        }
    }

    int i0 = blockIdx.y * 4;     // 4 i-values per tile (BM/32)
    int j0 = blockIdx.x * 4;
    #pragma unroll
    for (int p = 0; p < 2; p++) {
        int pr = pb + p;
        int i = i0 + (pr >> 2);
        int j = j0 + (pr & 3);
        #pragma unroll
        for (int q = 0; q < 4; q++) {
            z[(i * S_DIM + j) * CZ_DIM + zz0 + q] = zacc[p][q] + b_final[zz0 + q];
        }
    }
}

// ---------------------------------------------------------------------------
extern "C" void kernel_launch(void* const* d_in, const int* in_sizes, int n_in,
                              void* d_out, int out_size)
{
    const float* m_si    = (const float*)d_in[0];
    const float* ln_g    = (const float*)d_in[1];
    const float* ln_b    = (const float*)d_in[2];
    const float* w_ab    = (const float*)d_in[3];
    const float* w_final = (const float*)d_in[4];
    const float* b_final = (const float*)d_in[5];
    float* z = (float*)d_out;

    (void)in_sizes; (void)n_in; (void)out_size;

    ln_proj_kernel<<<(S_DIM * N_DIM) / 8, 256>>>(m_si, ln_g, ln_b, w_ab);

    const int smem_bytes = 16 * OSM_STRIDE * sizeof(float);   // 66048 B
    cudaFuncSetAttribute(opm_fused_kernel,
                         cudaFuncAttributeMaxDynamicSharedMemorySize, smem_bytes);
    dim3 grid(S_DIM / 4, S_DIM / 4);   // 96 x 96 CTAs
    opm_fused_kernel<<<grid, 256, smem_bytes>>>(w_final, b_final, z);
}

// round 6
// speedup vs baseline: 4.2010x; 4.2010x over previous
#include <cuda_runtime.h>
#include <cstdint>

#define S_DIM 384

__device__ float g_A[12288 * 512];   // [m = i*32+c][k=n]  (1/512 folded, tf32-rounded)
__device__ float g_B[12288 * 512];   // [p = j*32+d][k=n]  (tf32-rounded)
__device__ float g_W[128 * 1024];    // [zz][k' = d*32+c]  (permuted, tf32-rounded)

// ---------------------------------------------------------------- helpers
__device__ __forceinline__ uint32_t smem_u32(const void* p) {
    uint32_t a;
    asm("{ .reg .u64 t; cvta.to.shared.u64 t, %1; cvt.u32.u64 %0, t; }" : "=r"(a) : "l"(p));
    return a;
}
__device__ __forceinline__ float tf32rn(float x) {
    uint32_t r; asm("cvt.rna.tf32.f32 %0, %1;" : "=r"(r) : "f"(x));
    return __uint_as_float(r);
}
__device__ __forceinline__ uint32_t lds32(uint32_t a) {
    uint32_t v; asm volatile("ld.shared.b32 %0, [%1];" : "=r"(v) : "r"(a)); return v;
}
__device__ __forceinline__ void sts32(uint32_t a, float v) {
    asm volatile("st.shared.b32 [%0], %1;" :: "r"(a), "f"(v) : "memory");
}
__device__ __forceinline__ void cp16(uint32_t dst, const float* src) {
    asm volatile("cp.async.cg.shared.global [%0], [%1], 16;" :: "r"(dst), "l"(src));
}
#define CP_COMMIT() asm volatile("cp.async.commit_group;" ::: "memory")
#define CP_WAIT1()  asm volatile("cp.async.wait_group 1;" ::: "memory")
#define CP_WAIT0()  asm volatile("cp.async.wait_group 0;" ::: "memory")

// m16n8k8 tf32 MMA (base ISA, sm_80+): D += A*B
__device__ __forceinline__ void mma8(float* d, const uint32_t* a, uint32_t b0, uint32_t b1) {
    asm volatile(
        "mma.sync.aligned.m16n8k8.row.col.f32.tf32.tf32.f32 "
        "{%0,%1,%2,%3}, {%4,%5,%6,%7}, {%8,%9}, {%0,%1,%2,%3};"
        : "+f"(d[0]), "+f"(d[1]), "+f"(d[2]), "+f"(d[3])
        : "r"(a[0]), "r"(a[1]), "r"(a[2]), "r"(a[3]), "r"(b0), "r"(b1));
}

// ---------------------------------------------------------------- kernel 0: W permute+round
__global__ __launch_bounds__(256) void wprep_kernel(const float* __restrict__ w) {
    int i  = blockIdx.x * 256 + threadIdx.x;       // 131072
    int zz = i >> 10, kp = i & 1023;
    int d  = kp >> 5,  c = kp & 31;
    g_W[i] = tf32rn(w[zz * 1024 + c * 32 + d]);    // k' = d*32 + c
}

// ---------------------------------------------------------------- kernel 1: LN + projection
__global__ __launch_bounds__(256) void ln_proj_kernel(
    const float* __restrict__ m_si, const float* __restrict__ ln_g,
    const float* __restrict__ ln_b, const float* __restrict__ w_ab)
{
    extern __shared__ char smem_raw[];
    float* sm  = reinterpret_cast<float*>(smem_raw);
    float* ws  = sm;            // [64][33]
    float* a_s = sm + 2112;     // [32][513]
    float* b_s = sm + 18528;    // [32][513]

    int t = threadIdx.x, warp = t >> 5, lane = t & 31;
    int s = blockIdx.x;

    for (int idx = t; idx < 64 * 32; idx += 256)
        ws[(idx >> 5) * 33 + (idx & 31)] = w_ab[idx];
    __syncthreads();

    float g = ln_g[lane], bb = ln_b[lane];

    for (int it = 0; it < 64; it++) {
        int n = warp * 64 + it;
        float x = m_si[((size_t)(s * 512 + n)) * 32 + lane];

        float sum = x;
        #pragma unroll
        for (int o = 16; o; o >>= 1) sum += __shfl_xor_sync(0xFFFFFFFFu, sum, o);
        float mu = sum * (1.0f / 32.0f);
        float dx = x - mu;
        float v = dx * dx;
        #pragma unroll
        for (int o = 16; o; o >>= 1) v += __shfl_xor_sync(0xFFFFFFFFu, v, o);
        float mn = dx * rsqrtf(v * (1.0f / 32.0f) + 1e-5f) * g + bb;

        float aa = 0.0f, ab = 0.0f;
        #pragma unroll
        for (int c = 0; c < 32; c++) {
            float mc = __shfl_sync(0xFFFFFFFFu, mn, c);
            aa += mc * ws[lane * 33 + c];
            ab += mc * ws[(lane + 32) * 33 + c];
        }
        a_s[lane * 513 + n] = aa * (1.0f / 512.0f);
        b_s[lane * 513 + n] = ab;
    }
    __syncthreads();

    for (int q = 0; q < 64; q++) {
        int idx = q * 256 + t;
        int c = idx >> 9, n = idx & 511;
        g_A[((size_t)(s * 32 + c)) * 512 + n] = tf32rn(a_s[c * 513 + n]);
        g_B[((size_t)(s * 32 + c)) * 512 + n] = tf32rn(b_s[c * 513 + n]);
    }
}

// ---------------------------------------------------------------- kernel 2: fused tensor GEMMs
// SMEM map (bytes), mainloop:  sA0 0 (16K) | sA1 16384 | sB0 32768 (32K) | sB1 65536
// epilogue (reuse):  osm 0 (1024 x 40 floats = 160K) | W0 163840 (18K) | W1 182272
#define OFF_SB  32768u
#define OFF_WB  163840u
#define W_STRD  144u           // 36 floats per zz row
#define SMEM2   200704

__device__ __forceinline__ void load_AB(uint32_t sb, int ch, int buf, int m0, int p0, int t) {
    int k0 = ch * 32;
    uint32_t sA = sb + (buf ? 16384u : 0u);
    uint32_t sB = sb + OFF_SB + (buf ? 32768u : 0u);
    #pragma unroll
    for (int q = 0; q < 4; q++) {
        int idx = t + q * 256, row = idx >> 3, c = idx & 7;
        cp16(sA + row * 128u + ((uint32_t)(c ^ (row & 7)) << 4),
             g_A + (size_t)(m0 + row) * 512 + k0 + c * 4);
    }
    #pragma unroll
    for (int q = 0; q < 8; q++) {
        int idx = t + q * 256, row = idx >> 3, c = idx & 7;
        cp16(sB + row * 128u + ((uint32_t)(c ^ (row & 7)) << 4),
             g_B + (size_t)(p0 + row) * 512 + k0 + c * 4);
    }
}

__device__ __forceinline__ void load_W(uint32_t sb, int ch, int buf, int t) {
    uint32_t Wb = sb + OFF_WB + (buf ? 18432u : 0u);
    #pragma unroll
    for (int q = 0; q < 4; q++) {
        int idx = t + q * 256, zz = idx >> 3, c = idx & 7;
        cp16(Wb + zz * W_STRD + c * 16u,
             g_W + (size_t)zz * 1024 + ch * 32 + c * 4);
    }
}

__global__ __launch_bounds__(256) void opm_mma_kernel(
    const float* __restrict__ b_final, float* __restrict__ z)
{
    extern __shared__ char smem_raw[];
    uint32_t sb = smem_u32(smem_raw);

    int t = threadIdx.x, w = t >> 5, lane = t & 31;
    int g = lane >> 2, r = lane & 3;
    int wm = w >> 2, wn = w & 3;                  // warp grid 2(m) x 4(p)
    int m0 = blockIdx.y * 128, p0 = blockIdx.x * 256;
    uint32_t r4 = (uint32_t)r * 4u;

    float acc[4][8][4];
    #pragma unroll
    for (int i = 0; i < 4; i++)
        #pragma unroll
        for (int j = 0; j < 8; j++)
            #pragma unroll
            for (int cc = 0; cc < 4; cc++) acc[i][j][cc] = 0.0f;

    // ---- mainloop: o = A * B^T (K = 512, 16 chunks of 32, double-buffered)
    load_AB(sb, 0, 0, m0, p0, t); CP_COMMIT();
    load_AB(sb, 1, 1, m0, p0, t); CP_COMMIT();

    for (int s = 0; s < 16; s++) {
        int buf = s & 1;
        if (s < 15) CP_WAIT1(); else CP_WAIT0();
        __syncthreads();

        uint32_t sA = sb + (buf ? 16384u : 0u);
        uint32_t sB = sb + OFF_SB + (buf ? 32768u : 0u);

        #pragma unroll
        for (int ks = 0; ks < 4; ks++) {
            uint32_t off0 = (((uint32_t)((2 * ks) ^ g)) << 4) + r4;
            uint32_t off1 = (((uint32_t)((2 * ks + 1) ^ g)) << 4) + r4;

            uint32_t a[4][4];
            #pragma unroll
            for (int i = 0; i < 4; i++) {
                uint32_t rowb = sA + (uint32_t)(wm * 64 + i * 16 + g) * 128u;
                a[i][0] = lds32(rowb + off0);
                a[i][1] = lds32(rowb + 1024u + off0);   // row +8
                a[i][2] = lds32(rowb + off1);
                a[i][3] = lds32(rowb + 1024u + off1);
            }
            #pragma unroll
            for (int j = 0; j < 8; j++) {
                uint32_t prow = sB + (uint32_t)(wn * 64 + j * 8 + g) * 128u;
                uint32_t b0 = lds32(prow + off0);
                uint32_t b1 = lds32(prow + off1);
                #pragma unroll
                for (int i = 0; i < 4; i++) mma8(acc[i][j], a[i], b0, b1);
            }
        }
        __syncthreads();
        if (s + 2 < 16) { load_AB(sb, s + 2, buf, m0, p0, t); CP_COMMIT(); }
    }

    // ---- prefetch W chunks 0,1 while spilling o
    load_W(sb, 0, 0, t); CP_COMMIT();
    load_W(sb, 1, 1, t); CP_COMMIT();

    // ---- spill o to osm[k' = d*32+c][pair] (stride 40 floats), tf32-rounded
    #pragma unroll
    for (int i = 0; i < 4; i++)
        #pragma unroll
        for (int j = 0; j < 8; j++)
            #pragma unroll
            for (int cc = 0; cc < 4; cc++) {
                int m = wm * 64 + i * 16 + g + ((cc & 2) ? 8 : 0);
                int p = wn * 64 + j * 8 + 2 * r + (cc & 1);
                int kp   = (p & 31) * 32 + (m & 31);
                int pair = ((m >> 5) << 3) | (p >> 5);
                sts32(sb + (uint32_t)((kp * 40 + pair) * 4), tf32rn(acc[i][j][cc]));
            }
    __syncthreads();

    // ---- epilogue GEMM: z[zz][pair] = W' * o'  (M=128, N=32, K=1024; 32 W chunks)
    float zacc[4][4];
    #pragma unroll
    for (int j = 0; j < 4; j++)
        #pragma unroll
        for (int cc = 0; cc < 4; cc++) zacc[j][cc] = 0.0f;

    for (int ch = 0; ch < 32; ch++) {
        int buf = ch & 1;
        if (ch < 31) CP_WAIT1(); else CP_WAIT0();
        __syncthreads();

        uint32_t Wb = sb + OFF_WB + (buf ? 18432u : 0u);
        #pragma unroll
        for (int ks = 0; ks < 4; ks++) {
            int kb = ks * 8;
            uint32_t ar = Wb + (uint32_t)(w * 16 + g) * W_STRD + (uint32_t)(kb + r) * 4u;
            uint32_t aw[4];
            aw[0] = lds32(ar);            // (zz=w16+g,   k)
            aw[1] = lds32(ar + 1152u);    // (zz+8,       k)
            aw[2] = lds32(ar + 16u);      // (zz,         k+4)
            aw[3] = lds32(ar + 1168u);    // (zz+8,       k+4)

            uint32_t brow = sb + (uint32_t)(((ch * 32 + kb + r) * 40 + g) * 4);
            #pragma unroll
            for (int j = 0; j < 4; j++) {
                uint32_t b0 = lds32(brow + (uint32_t)(j * 32));           // pair = j*8+g, k
                uint32_t b1 = lds32(brow + 640u + (uint32_t)(j * 32));    // k+4
                mma8(zacc[j], aw, b0, b1);
            }
        }
        __syncthreads();
        if (ch + 2 < 32) { load_W(sb, ch + 2, buf, t); CP_COMMIT(); }
    }

    // ---- write z (+bias)
    float bf0 = b_final[w * 16 + g];
    float bf1 = b_final[w * 16 + g + 8];
    #pragma unroll
    for (int j = 0; j < 4; j++)
        #pragma unroll
        for (int cc = 0; cc < 4; cc++) {
            int zz = w * 16 + g + ((cc & 2) ? 8 : 0);
            int n  = j * 8 + 2 * r + (cc & 1);           // pair 0..31
            int ig = blockIdx.y * 4 + (n >> 3);
            int jg = blockIdx.x * 8 + (n & 7);
            z[((size_t)(ig * S_DIM + jg)) * 128 + zz] =
                zacc[j][cc] + ((cc & 2) ? bf1 : bf0);
        }
}

// ---------------------------------------------------------------- launch
extern "C" void kernel_launch(void* const* d_in, const int* in_sizes, int n_in,
                              void* d_out, int out_size)
{
    const float* m_si    = (const float*)d_in[0];
    const float* ln_g    = (const float*)d_in[1];
    const float* ln_b    = (const float*)d_in[2];
    const float* w_ab    = (const float*)d_in[3];
    const float* w_final = (const float*)d_in[4];
    const float* b_final = (const float*)d_in[5];
    float* z = (float*)d_out;
    (void)in_sizes; (void)n_in; (void)out_size;

    wprep_kernel<<<512, 256>>>(w_final);

    cudaFuncSetAttribute(ln_proj_kernel,
                         cudaFuncAttributeMaxDynamicSharedMemorySize, 139776);
    ln_proj_kernel<<<S_DIM, 256, 139776>>>(m_si, ln_g, ln_b, w_ab);

    cudaFuncSetAttribute(opm_mma_kernel,
                         cudaFuncAttributeMaxDynamicSharedMemorySize, SMEM2);
    dim3 grid(48, 96);   // (p-tiles, m-tiles)
    opm_mma_kernel<<<grid, 256, SMEM2>>>(b_final, z);
}